// round 3
// baseline (speedup 1.0000x reference)
#include <cuda_runtime.h>
#include <cstdint>
#include <cstddef>

#define TOK 16384
#define HD 1024
#define MD 2048
#define NE 16
#define RT (TOK*2)

// ---------------- scratch (device globals: allocation-free) ----------------
__device__ int   g_cnt[NE];
__device__ int   g_cur[NE];
__device__ int   g_offs[NE+1];
__device__ int   g_texp[RT];
__device__ float g_tw[RT];
__device__ int   g_ptok[RT];
__device__ float g_pw[RT];
__device__ int   g_pos[RT];
__device__ float g_hmid[(size_t)RT * MD];   // 268 MB fp32 intermediate
__device__ float g_y[(size_t)RT * HD];      // 134 MB per-(token,expert) outputs

// ---------------- helpers ----------------
__device__ __forceinline__ uint32_t f2tf(float x){
    uint32_t r; asm("cvt.rna.tf32.f32 %0, %1;" : "=r"(r) : "f"(x)); return r;
}

__device__ __forceinline__ void mma_tf32(float* c, const uint32_t* a, const uint32_t* b){
    asm volatile("mma.sync.aligned.m16n8k8.row.col.f32.tf32.tf32.f32 "
        "{%0,%1,%2,%3}, {%4,%5,%6,%7}, {%8,%9}, {%0,%1,%2,%3};"
        : "+f"(c[0]), "+f"(c[1]), "+f"(c[2]), "+f"(c[3])
        : "r"(a[0]), "r"(a[1]), "r"(a[2]), "r"(a[3]), "r"(b[0]), "r"(b[1]));
}

// ---------------- routing kernels ----------------
__global__ void init_kernel(){
    int i = threadIdx.x;
    if (i < NE){ g_cnt[i] = 0; g_cur[i] = 0; }
}

__global__ __launch_bounds__(256) void gate_kernel(const float* __restrict__ X,
        const float* __restrict__ Wg, const float* __restrict__ bg){
    int warp = threadIdx.x >> 5, lane = threadIdx.x & 31;
    int t = blockIdx.x * 8 + warp;
    float acc[NE];
    #pragma unroll
    for (int e = 0; e < NE; e++) acc[e] = 0.f;
    const float* xr = X + (size_t)t * HD;
    for (int h = lane; h < HD; h += 32){
        float x = xr[h];
        const float4* w4 = (const float4*)(Wg + (size_t)h * NE);
        #pragma unroll
        for (int j = 0; j < 4; j++){
            float4 w = w4[j];
            acc[4*j+0] += x * w.x; acc[4*j+1] += x * w.y;
            acc[4*j+2] += x * w.z; acc[4*j+3] += x * w.w;
        }
    }
    #pragma unroll
    for (int e = 0; e < NE; e++){
        #pragma unroll
        for (int off = 16; off; off >>= 1)
            acc[e] += __shfl_xor_sync(0xffffffffu, acc[e], off);
    }
    if (lane == 0){
        #pragma unroll
        for (int e = 0; e < NE; e++) acc[e] += bg[e];
        int i1 = 0;
        #pragma unroll
        for (int e = 1; e < NE; e++) if (acc[e] > acc[i1]) i1 = e;
        int i2 = (i1 == 0) ? 1 : 0;
        #pragma unroll
        for (int e = 0; e < NE; e++) if (e != i1 && acc[e] > acc[i2]) i2 = e;
        // renormalized top-2 softmax weights: w1 = e^l1/(e^l1+e^l2)
        float w1 = 1.f / (1.f + expf(acc[i2] - acc[i1]));
        float w2 = 1.f - w1;
        g_texp[2*t]   = i1; g_tw[2*t]   = w1;
        g_texp[2*t+1] = i2; g_tw[2*t+1] = w2;
        atomicAdd(&g_cnt[i1], 1); atomicAdd(&g_cnt[i2], 1);
    }
}

__global__ void scan_kernel(){
    if (threadIdx.x == 0){
        int s = 0;
        for (int e = 0; e < NE; e++){ g_offs[e] = s; s += g_cnt[e]; }
        g_offs[NE] = s;
    }
}

__global__ __launch_bounds__(256) void scatter_kernel(){
    int i = blockIdx.x * 256 + threadIdx.x;   // i < RT
    int e = g_texp[i];
    int p = g_offs[e] + atomicAdd(&g_cur[e], 1);
    g_ptok[p] = i >> 1;
    g_pw[p]   = g_tw[i];
    g_pos[i]  = p;
}

// ---------------- grouped GEMM (tf32 mma.sync) ----------------
// PHASE 1: Hmid[p,:] = relu(X[tok(p),:] @ W1[e] + b1[e])   (KD=HD, ND=MD)
// PHASE 2: Y[p,:]    = w(p) * (Hmid[p,:] @ W2[e] + b2[e])  (KD=MD, ND=HD)
template<int KD, int ND, int PHASE>
__global__ __launch_bounds__(256, 2)
void moe_gemm(const float* __restrict__ Xin,
              const float* __restrict__ Wbase,
              const float* __restrict__ bias)
{
    constexpr int BM = 128, BN = 128, BK = 32;
    const int e = blockIdx.z;
    const int start = g_offs[e];
    const int rows  = g_offs[e+1] - start;
    const int m0 = blockIdx.y * BM;
    if (m0 >= rows) return;
    const int n0 = blockIdx.x * BN;

    const float* Abase = (PHASE == 1) ? Xin : g_hmid;
    float*       Cbase = (PHASE == 1) ? g_hmid : g_y;

    __shared__ float As[BM][36];    // stride 36: conflict-free frag loads
    __shared__ float Bs[BK][136];   // stride 136: conflict-free frag loads

    const int tid  = threadIdx.x;
    const int arow = tid >> 3;      // 0..31
    const int aseg = tid & 7;       // k-offset = aseg*4
    const float* aptr[4];
    bool av[4];
    #pragma unroll
    for (int i = 0; i < 4; i++){
        int gr = m0 + arow + 32*i;
        bool v = gr < rows;
        av[i] = v;
        size_t rowidx;
        if (PHASE == 1) rowidx = (size_t)(v ? g_ptok[start + gr] : 0);
        else            rowidx = (size_t)(start + (v ? gr : 0));
        aptr[i] = Abase + rowidx * KD + aseg * 4;
    }
    const int bkr = tid >> 5;   // 0..7
    const int bn4 = tid & 31;
    const float* Wp = Wbase + (size_t)e * KD * ND + n0 + bn4 * 4;

    float cc[4][4][4];
    #pragma unroll
    for (int a = 0; a < 4; a++)
        #pragma unroll
        for (int b = 0; b < 4; b++)
            #pragma unroll
            for (int c = 0; c < 4; c++) cc[a][b][c] = 0.f;

    const int warp = tid >> 5, lane = tid & 31;
    const int wm = (warp & 1) * 64;     // 2x4 warp grid, warp tile 64x32
    const int wn = (warp >> 1) * 32;
    const int g  = lane >> 2, tq = lane & 3;

    for (int kb = 0; kb < KD; kb += BK){
        #pragma unroll
        for (int i = 0; i < 4; i++){
            float4 v = av[i] ? *(const float4*)(aptr[i] + kb)
                             : make_float4(0.f, 0.f, 0.f, 0.f);
            uint4 u;
            u.x = f2tf(v.x); u.y = f2tf(v.y); u.z = f2tf(v.z); u.w = f2tf(v.w);
            *(uint4*)&As[arow + 32*i][aseg * 4] = u;
        }
        #pragma unroll
        for (int i = 0; i < 4; i++){
            int k = bkr + 8*i;
            float4 v = *(const float4*)(Wp + (size_t)(kb + k) * ND);
            uint4 u;
            u.x = f2tf(v.x); u.y = f2tf(v.y); u.z = f2tf(v.z); u.w = f2tf(v.w);
            *(uint4*)&Bs[k][bn4 * 4] = u;
        }
        __syncthreads();
        #pragma unroll
        for (int k8 = 0; k8 < 4; k8++){
            const int kc = k8 * 8;
            uint32_t af[4][4];
            uint32_t bf[4][2];
            #pragma unroll
            for (int mt = 0; mt < 4; mt++){
                const int m = wm + mt * 16;
                af[mt][0] = __float_as_uint(As[m + g    ][kc + tq    ]);
                af[mt][1] = __float_as_uint(As[m + g + 8][kc + tq    ]);
                af[mt][2] = __float_as_uint(As[m + g    ][kc + tq + 4]);
                af[mt][3] = __float_as_uint(As[m + g + 8][kc + tq + 4]);
            }
            #pragma unroll
            for (int nt = 0; nt < 4; nt++){
                const int n = wn + nt * 8;
                bf[nt][0] = __float_as_uint(Bs[kc + tq    ][n + g]);
                bf[nt][1] = __float_as_uint(Bs[kc + tq + 4][n + g]);
            }
            #pragma unroll
            for (int mt = 0; mt < 4; mt++)
                #pragma unroll
                for (int nt = 0; nt < 4; nt++)
                    mma_tf32(cc[mt][nt], af[mt], bf[nt]);
        }
        __syncthreads();
    }

    // epilogue
    float wrow0[4], wrow1[4];
    if (PHASE == 2){
        #pragma unroll
        for (int mt = 0; mt < 4; mt++){
            int r0 = m0 + wm + mt * 16 + g;
            wrow0[mt] = (r0     < rows) ? g_pw[start + r0    ] : 0.f;
            wrow1[mt] = (r0 + 8 < rows) ? g_pw[start + r0 + 8] : 0.f;
        }
    }
    const float* be = bias + (size_t)e * ND;
    #pragma unroll
    for (int mt = 0; mt < 4; mt++){
        int r0 = m0 + wm + mt * 16 + g;
        #pragma unroll
        for (int nt = 0; nt < 4; nt++){
            int n = n0 + wn + nt * 8 + 2 * tq;
            float b0v = be[n], b1v = be[n + 1];
            float v00 = cc[mt][nt][0] + b0v, v01 = cc[mt][nt][1] + b1v;
            float v10 = cc[mt][nt][2] + b0v, v11 = cc[mt][nt][3] + b1v;
            if (PHASE == 1){
                v00 = fmaxf(v00, 0.f); v01 = fmaxf(v01, 0.f);
                v10 = fmaxf(v10, 0.f); v11 = fmaxf(v11, 0.f);
            } else {
                v00 *= wrow0[mt]; v01 *= wrow0[mt];
                v10 *= wrow1[mt]; v11 *= wrow1[mt];
            }
            if (r0 < rows)
                *(float2*)&Cbase[(size_t)(start + r0) * ND + n] = make_float2(v00, v01);
            if (r0 + 8 < rows)
                *(float2*)&Cbase[(size_t)(start + r0 + 8) * ND + n] = make_float2(v10, v11);
        }
    }
}

// ---------------- combine: out[t] = Y[pos(t,0)] + Y[pos(t,1)] ----------------
__global__ __launch_bounds__(256) void combine_kernel(float* __restrict__ out){
    size_t idx = (size_t)blockIdx.x * 256 + threadIdx.x;
    int t = (int)(idx >> 8);          // 256 float4 per token (HD/4)
    int j = (int)(idx & 255);
    int p0 = g_pos[2 * t], p1 = g_pos[2 * t + 1];
    const float4* Y4 = (const float4*)g_y;
    float4 a = Y4[(size_t)p0 * (HD / 4) + j];
    float4 b = Y4[(size_t)p1 * (HD / 4) + j];
    ((float4*)out)[idx] = make_float4(a.x + b.x, a.y + b.y, a.z + b.z, a.w + b.w);
}

// ---------------- launch ----------------
extern "C" void kernel_launch(void* const* d_in, const int* in_sizes, int n_in,
                              void* d_out, int out_size) {
    const float* X  = (const float*)d_in[0];
    const float* Wg = (const float*)d_in[1];
    const float* bg = (const float*)d_in[2];
    const float* W1 = (const float*)d_in[3];
    const float* b1 = (const float*)d_in[4];
    const float* W2 = (const float*)d_in[5];
    const float* b2 = (const float*)d_in[6];
    float* out = (float*)d_out;

    init_kernel<<<1, 32>>>();
    gate_kernel<<<TOK / 8, 256>>>(X, Wg, bg);
    scan_kernel<<<1, 32>>>();
    scatter_kernel<<<RT / 256, 256>>>();
    moe_gemm<HD, MD, 1><<<dim3(MD / 128, TOK / 128, NE), 256>>>(X, W1, b1);
    moe_gemm<MD, HD, 2><<<dim3(HD / 128, TOK / 128, NE), 256>>>(X, W2, b2);
    combine_kernel<<<TOK * HD / 1024, 256>>>(out);
}

// round 6
// speedup vs baseline: 1.5817x; 1.5817x over previous
#include <cuda_runtime.h>
#include <cuda_fp16.h>
#include <cstdint>
#include <cstddef>

#define TOK 16384
#define HD 1024
#define MD 2048
#define NE 16
#define RT (TOK*2)

// ---------------- scratch (device globals: allocation-free) ----------------
__device__ int    g_cnt[NE];
__device__ int    g_cur[NE];
__device__ int    g_offs[NE+1];
__device__ int    g_texp[RT];
__device__ float  g_tw[RT];
__device__ int    g_ptok[RT];
__device__ float  g_pw[RT];
__device__ int    g_pos[RT];
__device__ __half g_xah [(size_t)RT * HD];      // gathered A, fp16 (67MB)
__device__ __half g_w1h [(size_t)NE * HD * MD]; // W1 fp16, original [e][k][n] layout
__device__ __half g_w2h [(size_t)NE * MD * HD]; // W2 fp16, original [e][k][n] layout
__device__ __half g_hmidh[(size_t)RT * MD];     // intermediate, fp16 (134MB)
__device__ float  g_y   [(size_t)RT * HD];      // per-(token,expert) outputs fp32

// ---------------- helpers ----------------
__device__ __forceinline__ uint32_t smem_u32(const void* p){
    uint32_t a;
    asm("{ .reg .u64 t; cvta.to.shared.u64 t, %1; cvt.u32.u64 %0, t; }" : "=r"(a) : "l"(p));
    return a;
}
__device__ __forceinline__ void cpa16(uint32_t dst, const void* src, bool valid){
    asm volatile("cp.async.cg.shared.global [%0], [%1], 16, %2;\n"
                 :: "r"(dst), "l"(src), "r"(valid ? 16 : 0) : "memory");
}
__device__ __forceinline__ void ldsm4(uint32_t* r, uint32_t addr){
    asm volatile("ldmatrix.sync.aligned.m8n8.x4.shared.b16 {%0,%1,%2,%3}, [%4];"
                 : "=r"(r[0]), "=r"(r[1]), "=r"(r[2]), "=r"(r[3]) : "r"(addr));
}
__device__ __forceinline__ void ldsm4t(uint32_t* r, uint32_t addr){
    asm volatile("ldmatrix.sync.aligned.m8n8.x4.trans.shared.b16 {%0,%1,%2,%3}, [%4];"
                 : "=r"(r[0]), "=r"(r[1]), "=r"(r[2]), "=r"(r[3]) : "r"(addr));
}
__device__ __forceinline__ void mma_f16(float* c, const uint32_t* a, const uint32_t* b){
    asm volatile("mma.sync.aligned.m16n8k16.row.col.f32.f16.f16.f32 "
        "{%0,%1,%2,%3}, {%4,%5,%6,%7}, {%8,%9}, {%0,%1,%2,%3};"
        : "+f"(c[0]), "+f"(c[1]), "+f"(c[2]), "+f"(c[3])
        : "r"(a[0]), "r"(a[1]), "r"(a[2]), "r"(a[3]), "r"(b[0]), "r"(b[1]));
}

// ---------------- routing kernels ----------------
__global__ void init_kernel(){
    int i = threadIdx.x;
    if (i < NE){ g_cnt[i] = 0; g_cur[i] = 0; }
}

__global__ __launch_bounds__(256) void gate_kernel(const float* __restrict__ X,
        const float* __restrict__ Wg, const float* __restrict__ bg){
    int warp = threadIdx.x >> 5, lane = threadIdx.x & 31;
    int t = blockIdx.x * 8 + warp;
    float acc[NE];
    #pragma unroll
    for (int e = 0; e < NE; e++) acc[e] = 0.f;
    const float* xr = X + (size_t)t * HD;
    for (int h = lane; h < HD; h += 32){
        float x = xr[h];
        const float4* w4 = (const float4*)(Wg + (size_t)h * NE);
        #pragma unroll
        for (int j = 0; j < 4; j++){
            float4 w = w4[j];
            acc[4*j+0] += x * w.x; acc[4*j+1] += x * w.y;
            acc[4*j+2] += x * w.z; acc[4*j+3] += x * w.w;
        }
    }
    #pragma unroll
    for (int e = 0; e < NE; e++){
        #pragma unroll
        for (int off = 16; off; off >>= 1)
            acc[e] += __shfl_xor_sync(0xffffffffu, acc[e], off);
    }
    if (lane == 0){
        #pragma unroll
        for (int e = 0; e < NE; e++) acc[e] += bg[e];
        int i1 = 0;
        #pragma unroll
        for (int e = 1; e < NE; e++) if (acc[e] > acc[i1]) i1 = e;
        int i2 = (i1 == 0) ? 1 : 0;
        #pragma unroll
        for (int e = 0; e < NE; e++) if (e != i1 && acc[e] > acc[i2]) i2 = e;
        float w1 = 1.f / (1.f + expf(acc[i2] - acc[i1]));
        float w2 = 1.f - w1;
        g_texp[2*t]   = i1; g_tw[2*t]   = w1;
        g_texp[2*t+1] = i2; g_tw[2*t+1] = w2;
        atomicAdd(&g_cnt[i1], 1); atomicAdd(&g_cnt[i2], 1);
    }
}

__global__ void scan_kernel(){
    if (threadIdx.x == 0){
        int s = 0;
        for (int e = 0; e < NE; e++){ g_offs[e] = s; s += g_cnt[e]; }
        g_offs[NE] = s;
    }
}

__global__ __launch_bounds__(256) void scatter_kernel(){
    int i = blockIdx.x * 256 + threadIdx.x;
    int e = g_texp[i];
    int p = g_offs[e] + atomicAdd(&g_cur[e], 1);
    g_ptok[p] = i >> 1;
    g_pw[p]   = g_tw[i];
    g_pos[i]  = p;
}

// ---------------- pre-passes: fp32 -> fp16 ----------------
__global__ __launch_bounds__(256) void cvt_half_kernel(const float* __restrict__ src,
                                                       __half* __restrict__ dst){
    size_t i = (size_t)blockIdx.x * 256 + threadIdx.x;   // one float4 per thread
    float4 v = ((const float4*)src)[i];
    __half2* d2 = (__half2*)dst;
    d2[2*i]   = __floats2half2_rn(v.x, v.y);
    d2[2*i+1] = __floats2half2_rn(v.z, v.w);
}

__global__ __launch_bounds__(256) void gather_cvt(const float* __restrict__ X){
    int p = blockIdx.x;
    int t = g_ptok[p];
    float4 v = ((const float4*)(X + (size_t)t * HD))[threadIdx.x];
    __half2* d2 = (__half2*)(g_xah + (size_t)p * HD);
    d2[2*threadIdx.x]   = __floats2half2_rn(v.x, v.y);
    d2[2*threadIdx.x+1] = __floats2half2_rn(v.z, v.w);
}

// ---------------- fp16 grouped GEMM, 4-stage cp.async pipeline ----------------
// PHASE 1: hmid[p,:] = f16(relu(xa[p,:] @ W1[e] + b1[e]))   (KD=HD, ND=MD)
// PHASE 2: y[p,:]    = pw(p) * (hmid[p,:] @ W2[e] + b2[e])  (KD=MD, ND=HD)
static constexpr int GEMM_SMEM = 1024 + 4*(128*40*2) + 4*(32*264*2);  // 109568

template<int KD, int ND, int PHASE>
__global__ __launch_bounds__(256, 1)
void moe_gemm_h(const float* __restrict__ bias)
{
    constexpr int BM = 128, BN = 256, BK = 32, S = 4;
    constexpr int NC = KD / BK;
    constexpr int ASTRB = 80;     // bytes per A SMEM row (32 halves + 8 pad)
    constexpr int BSTRB = 528;    // bytes per B SMEM row (256 halves + 8 pad)
    constexpr int ABYTES = BM * ASTRB;   // 10240
    constexpr int BBYTES = BK * BSTRB;   // 16896
    extern __shared__ char smem[];
    float* bias_s = (float*)smem;
    const uint32_t As0 = smem_u32(smem + 1024);
    const uint32_t Bs0 = As0 + S * ABYTES;

    const int e = blockIdx.z;
    const int start = g_offs[e];
    const int rows  = g_offs[e+1] - start;
    const int m0 = blockIdx.y * BM;
    if (m0 >= rows) return;
    const int n0 = blockIdx.x * BN;
    const int tid = threadIdx.x, wid = tid >> 5, lane = tid & 31;

    const __half* Ab = (PHASE == 1) ? (const __half*)g_xah : (const __half*)g_hmidh;
    const __half* Wh = (PHASE == 1) ? (const __half*)g_w1h : (const __half*)g_w2h;

    bias_s[tid] = bias[(size_t)e * ND + n0 + tid];

    // staging assignment
    const int ar = tid >> 1, ac = tid & 1;          // A: row, 32B-half
    const bool a_ok = (m0 + ar) < rows;
    const __half* a_srcrow = Ab + (size_t)(start + m0 + (a_ok ? ar : 0)) * KD + ac * 16;
    const uint32_t a_doff = (uint32_t)(ar * ASTRB + ac * 32);
    const int br = tid >> 3, bc = tid & 7;          // B: k-row, 64B col chunk
    const __half* b_srcrow = Wh + ((size_t)e * KD + br) * ND + n0 + bc * 32;
    const uint32_t b_doff = (uint32_t)(br * BSTRB + bc * 64);

    auto stage = [&](int c, int slot){
        uint32_t Abase = As0 + slot * ABYTES;
        uint32_t Bbase = Bs0 + slot * BBYTES;
        const __half* as = a_srcrow + c * BK;
        cpa16(Abase + a_doff,      as,     a_ok);
        cpa16(Abase + a_doff + 16, as + 8, a_ok);
        const __half* bs = b_srcrow + (size_t)c * BK * ND;
        #pragma unroll
        for (int j = 0; j < 4; j++) cpa16(Bbase + b_doff + j*16, bs + j*8, true);
    };

    // prologue: stages 0..S-2
    #pragma unroll
    for (int i = 0; i < S-1; i++){
        stage(i, i);
        asm volatile("cp.async.commit_group;" ::: "memory");
    }

    // per-lane fragment addressing
    const int wm = (wid & 1) * 64, wn = (wid >> 1) * 64;
    const int g = lane >> 3, lr = lane & 7, gq = lane >> 2, tq = lane & 3;
    const uint32_t aoff = (uint32_t)((wm + (g & 1) * 8 + lr) * ASTRB + (g >> 1) * 16);
    const uint32_t boff = (uint32_t)(((g & 1) * 8 + lr) * BSTRB + (g >> 1) * 16 + wn * 2);

    float c[4][8][4];
    #pragma unroll
    for (int a = 0; a < 4; a++)
        #pragma unroll
        for (int b = 0; b < 8; b++)
            #pragma unroll
            for (int k = 0; k < 4; k++) c[a][b][k] = 0.f;

    for (int i = 0; i < NC; i++){
        asm volatile("cp.async.wait_group %0;" :: "n"(S-2) : "memory");
        __syncthreads();
        if (i + S - 1 < NC) stage(i + S - 1, (i + S - 1) & (S - 1));
        asm volatile("cp.async.commit_group;" ::: "memory");

        const uint32_t Abase = As0 + (i & (S-1)) * ABYTES + aoff;
        const uint32_t Bbase = Bs0 + (i & (S-1)) * BBYTES + boff;
        #pragma unroll
        for (int ks = 0; ks < 2; ks++){
            uint32_t af[4][4], bf[4][4];
            #pragma unroll
            for (int mt = 0; mt < 4; mt++)
                ldsm4(af[mt], Abase + mt * (16 * ASTRB) + ks * 32);
            #pragma unroll
            for (int nt = 0; nt < 4; nt++)
                ldsm4t(bf[nt], Bbase + ks * (16 * BSTRB) + nt * 32);
            #pragma unroll
            for (int mt = 0; mt < 4; mt++)
                #pragma unroll
                for (int nt = 0; nt < 4; nt++){
                    mma_f16(c[mt][2*nt],   af[mt], bf[nt]);
                    mma_f16(c[mt][2*nt+1], af[mt], bf[nt] + 2);
                }
        }
    }

    // ---------------- epilogue ----------------
    #pragma unroll
    for (int mt = 0; mt < 4; mt++){
        const int r0l = wm + mt * 16 + gq;
        const int r1l = r0l + 8;
        const bool v0 = (m0 + r0l) < rows;
        const bool v1 = (m0 + r1l) < rows;
        const size_t gr0 = (size_t)(start + m0 + (v0 ? r0l : 0));
        const size_t gr1 = (size_t)(start + m0 + (v1 ? r1l : 0));
        float pw0 = 0.f, pw1 = 0.f;
        if (PHASE == 2){
            pw0 = v0 ? g_pw[gr0] : 0.f;
            pw1 = v1 ? g_pw[gr1] : 0.f;
        }
        #pragma unroll
        for (int j = 0; j < 8; j++){
            const int nw = (j >> 1) * 16 + (j & 1) * 8;
            const int n = wn + nw + 2 * tq;
            const float bb0 = bias_s[n], bb1 = bias_s[n + 1];
            float v00 = c[mt][j][0] + bb0, v01 = c[mt][j][1] + bb1;
            float v10 = c[mt][j][2] + bb0, v11 = c[mt][j][3] + bb1;
            if (PHASE == 1){
                if (v0)
                    *(__half2*)(g_hmidh + gr0 * ND + n0 + n) =
                        __floats2half2_rn(fmaxf(v00, 0.f), fmaxf(v01, 0.f));
                if (v1)
                    *(__half2*)(g_hmidh + gr1 * ND + n0 + n) =
                        __floats2half2_rn(fmaxf(v10, 0.f), fmaxf(v11, 0.f));
            } else {
                if (v0)
                    *(float2*)(g_y + gr0 * ND + n0 + n) = make_float2(v00 * pw0, v01 * pw0);
                if (v1)
                    *(float2*)(g_y + gr1 * ND + n0 + n) = make_float2(v10 * pw1, v11 * pw1);
            }
        }
    }
}

// ---------------- combine: out[t] = Y[pos(t,0)] + Y[pos(t,1)] ----------------
__global__ __launch_bounds__(256) void combine_kernel(float* __restrict__ out){
    size_t idx = (size_t)blockIdx.x * 256 + threadIdx.x;
    int t = (int)(idx >> 8);
    int j = (int)(idx & 255);
    int p0 = g_pos[2 * t], p1 = g_pos[2 * t + 1];
    const float4* Y4 = (const float4*)g_y;
    float4 a = Y4[(size_t)p0 * (HD / 4) + j];
    float4 b = Y4[(size_t)p1 * (HD / 4) + j];
    ((float4*)out)[idx] = make_float4(a.x + b.x, a.y + b.y, a.z + b.z, a.w + b.w);
}

// ---------------- launch ----------------
extern "C" void kernel_launch(void* const* d_in, const int* in_sizes, int n_in,
                              void* d_out, int out_size) {
    const float* X  = (const float*)d_in[0];
    const float* Wg = (const float*)d_in[1];
    const float* bg = (const float*)d_in[2];
    const float* W1 = (const float*)d_in[3];
    const float* b1 = (const float*)d_in[4];
    const float* W2 = (const float*)d_in[5];
    const float* b2 = (const float*)d_in[6];
    float* out = (float*)d_out;

    cudaFuncSetAttribute(moe_gemm_h<HD, MD, 1>,
                         cudaFuncAttributeMaxDynamicSharedMemorySize, GEMM_SMEM);
    cudaFuncSetAttribute(moe_gemm_h<MD, HD, 2>,
                         cudaFuncAttributeMaxDynamicSharedMemorySize, GEMM_SMEM);

    __half* w1h; cudaGetSymbolAddress((void**)&w1h, g_w1h);
    __half* w2h; cudaGetSymbolAddress((void**)&w2h, g_w2h);

    init_kernel<<<1, 32>>>();
    gate_kernel<<<TOK / 8, 256>>>(X, Wg, bg);
    scan_kernel<<<1, 32>>>();
    scatter_kernel<<<RT / 256, 256>>>();
    gather_cvt<<<RT, 256>>>(X);
    cvt_half_kernel<<<(int)(((size_t)NE*HD*MD/4) / 256), 256>>>(W1, w1h);
    cvt_half_kernel<<<(int)(((size_t)NE*MD*HD/4) / 256), 256>>>(W2, w2h);
    moe_gemm_h<HD, MD, 1><<<dim3(MD / 256, RT / 128, NE), 256, GEMM_SMEM>>>(b1);
    moe_gemm_h<MD, HD, 2><<<dim3(HD / 256, RT / 128, NE), 256, GEMM_SMEM>>>(b2);
    combine_kernel<<<TOK * HD / 1024, 256>>>(out);
}